// round 14
// baseline (speedup 1.0000x reference)
#include <cuda_runtime.h>
#include <cstdint>

// ---------------- problem constants ----------------
#define CDIM 128
#define MAXN 25600
#define MAXE 404000
#define TILE 128            // node tile rows
#define ETILE 64            // edge tile rows
#define WSTHREADS 512       // 8 consumer + 8 producer warps
#define GRIDX 148

// ---------------- device scratch ----------------
__device__ float g_K[(size_t)MAXN * CDIM];
__device__ float g_V[(size_t)MAXN * CDIM];
__device__ float g_R[(size_t)MAXN * CDIM];

// ---------------- helpers ----------------
__device__ __forceinline__ uint32_t smem_u32(const void* p) {
    return (uint32_t)__cvta_generic_to_shared(p);
}

// swizzled byte offset within a (rows x 256B) tile (16B chunks)
__device__ __forceinline__ uint32_t swz(int row, int chunk) {
    return (uint32_t)(row * 256) + (uint32_t)(((chunk ^ (row & 7)) << 4));
}

// pack two floats -> bf16x2 (lo=a, hi=b) + residual
__device__ __forceinline__ void split2(float a, float b, uint32_t& h, uint32_t& l) {
    asm("cvt.rn.bf16x2.f32 %0, %1, %2;" : "=r"(h) : "f"(b), "f"(a));
    float fa = __uint_as_float(h << 16);
    float fb = __uint_as_float(h & 0xFFFF0000u);
    float ra = a - fa, rb = b - fb;
    asm("cvt.rn.bf16x2.f32 %0, %1, %2;" : "=r"(l) : "f"(rb), "f"(ra));
}

// Fill W tiles with COLUMN PERMUTATION (see R11): thread t of consumer warp wn
// accumulates 8 consecutive output columns col0 = wn*32 + 8t.
__device__ __forceinline__ void fill_W_split(char* Whi, char* Wlo,
                                             const float* __restrict__ W,
                                             int tid, int nthreads) {
    for (int idx = tid; idx < 128 * 16; idx += nthreads) {
        int j = idx >> 4, ci = idx & 15;   // j = DEST smem row
        int w32 = j & ~31;
        int r   = j & 31;
        int nb  = r >> 3;
        int rho = r & 7;
        int c = w32 + ((rho >> 1) << 3) + (nb << 1) + (rho & 1);  // source W col
        const float4* w4 = (const float4*)(W + (size_t)c * CDIM + ci * 8);
        float4 f0 = w4[0], f1 = w4[1];
        uint4 h, l;
        split2(f0.x, f0.y, h.x, l.x);
        split2(f0.z, f0.w, h.y, l.y);
        split2(f1.x, f1.y, h.z, l.z);
        split2(f1.z, f1.w, h.w, l.w);
        uint32_t off = swz(j, ci);
        *(uint4*)(Whi + off) = h;
        *(uint4*)(Wlo + off) = l;
    }
}

__device__ __forceinline__ void ldsm_x4(uint32_t* r, uint32_t addr) {
    asm volatile("ldmatrix.sync.aligned.m8n8.x4.shared.b16 {%0,%1,%2,%3}, [%4];"
                 : "=r"(r[0]), "=r"(r[1]), "=r"(r[2]), "=r"(r[3]) : "r"(addr));
}

__device__ __forceinline__ void mma_bf16(float* d, const uint32_t* a, const uint32_t* b) {
    asm volatile(
        "mma.sync.aligned.m16n8k16.row.col.f32.bf16.bf16.f32 "
        "{%0,%1,%2,%3}, {%4,%5,%6,%7}, {%8,%9}, {%0,%1,%2,%3};"
        : "+f"(d[0]), "+f"(d[1]), "+f"(d[2]), "+f"(d[3])
        : "r"(a[0]), "r"(a[1]), "r"(a[2]), "r"(a[3]), "r"(b[0]), "r"(b[1]));
}

__device__ __forceinline__ void mbar_init(uint32_t mbar, uint32_t cnt) {
    asm volatile("mbarrier.init.shared.b64 [%0], %1;" :: "r"(mbar), "r"(cnt) : "memory");
}
__device__ __forceinline__ void mbar_arrive(uint32_t mbar) {
    asm volatile("mbarrier.arrive.release.cta.shared::cta.b64 _, [%0];"
                 :: "r"(mbar) : "memory");
}
__device__ __forceinline__ void mbar_wait(uint32_t mbar, uint32_t parity) {
    asm volatile(
        "{\n\t.reg .pred P;\n"
        "W_%=:\n\t"
        "mbarrier.try_wait.parity.acquire.cta.shared::cta.b64 P, [%0], %1, 0x989680;\n\t"
        "@P bra.uni D_%=;\n\t"
        "bra.uni W_%=;\n"
        "D_%=:\n\t}"
        :: "r"(mbar), "r"(parity) : "memory");
}

#define BARSYNC(id, n) asm volatile("bar.sync %0, %1;" :: "r"(id), "r"(n) : "memory")

// edge smem: Whi 32K | Wlo 32K | 4 stages x (Phi 16K | Plo 16K) | ctrl
// node smem: Whi 32K | Wlo 32K | Pbuf0 64K | Pbuf1 64K | ctrl
#define WS_SMEM (196608 + 128)

// detect int64 indices: odd 32-bit words of first 64 entries are all zero
__device__ __forceinline__ int detect_is64(const void* sraw, int lane) {
    const int* w = (const int*)sraw;
    int v = w[lane * 4 + 1] | w[lane * 4 + 3];
    return __any_sync(0xffffffffu, v != 0) ? 0 : 1;
}

// ---------------- producer row store: lane l owns channels [4l, 4l+4) ----------------
__device__ __forceinline__ void prod_store_row(char* Phi, char* Plo, int row, int lane,
                                               float p0, float p1, float p2, float p3) {
    uint32_t h0, l0, h1, l1;
    split2(p0, p1, h0, l0);
    split2(p2, p3, h1, l1);
    uint32_t off = swz(row, lane >> 1) + (lane & 1) * 8;
    uint2 h; h.x = h0; h.y = h1;
    uint2 l; l.x = l0; l.y = l1;
    *(uint2*)(Phi + off) = h;
    *(uint2*)(Plo + off) = l;
}

// ---------------- consumer GEMM: 64x32 warp tile (node) ----------------
__device__ __forceinline__ void consumer_gemm(uint32_t sPhi, uint32_t sPlo,
                                              uint32_t sWhi, uint32_t sWlo,
                                              int wm, int wn, int lane,
                                              float acc[4][4][4]) {
#pragma unroll
    for (int mb = 0; mb < 4; ++mb)
#pragma unroll
        for (int nb = 0; nb < 4; ++nb)
#pragma unroll
            for (int q = 0; q < 4; ++q) acc[mb][nb][q] = 0.f;

    int br0 = wn * 32 + (lane & 7) + ((lane >> 4) << 3);
    int ar_base = wm * 64 + (lane & 15);
    int cb = (lane >> 3) & 1;
    int ca = lane >> 4;

#pragma unroll
    for (int ks = 0; ks < 8; ++ks) {
        uint32_t Bh0[4], Bh1[4], Bl0[4], Bl1[4];
        uint32_t Ah[4][4], Al[4][4];
        {
            uint32_t offb0 = swz(br0, ks * 2 + cb);
            uint32_t offb1 = swz(br0 + 16, ks * 2 + cb);
            ldsm_x4(Bh0, sWhi + offb0);
            ldsm_x4(Bl0, sWlo + offb0);
            ldsm_x4(Bh1, sWhi + offb1);
            ldsm_x4(Bl1, sWlo + offb1);
        }
#pragma unroll
        for (int m = 0; m < 4; ++m) {
            uint32_t offa = swz(ar_base + m * 16, ks * 2 + ca);
            ldsm_x4(Ah[m], sPhi + offa);
            ldsm_x4(Al[m], sPlo + offa);
        }
#pragma unroll
        for (int mb = 0; mb < 4; ++mb) {
            mma_bf16(acc[mb][0], Ah[mb], Bh0);
            mma_bf16(acc[mb][0], Al[mb], Bh0);
            mma_bf16(acc[mb][0], Ah[mb], Bl0);
            mma_bf16(acc[mb][1], Ah[mb], Bh0 + 2);
            mma_bf16(acc[mb][1], Al[mb], Bh0 + 2);
            mma_bf16(acc[mb][1], Ah[mb], Bl0 + 2);
            mma_bf16(acc[mb][2], Ah[mb], Bh1);
            mma_bf16(acc[mb][2], Al[mb], Bh1);
            mma_bf16(acc[mb][2], Ah[mb], Bl1);
            mma_bf16(acc[mb][3], Ah[mb], Bh1 + 2);
            mma_bf16(acc[mb][3], Al[mb], Bh1 + 2);
            mma_bf16(acc[mb][3], Ah[mb], Bl1 + 2);
        }
    }
}

// ---------------- consumer GEMM: 32x32 warp tile (edge, 64-row tiles) ----------------
__device__ __forceinline__ void consumer_gemm32(uint32_t sPhi, uint32_t sPlo,
                                                uint32_t sWhi, uint32_t sWlo,
                                                int wm, int wn, int lane,
                                                float acc[2][4][4]) {
#pragma unroll
    for (int mb = 0; mb < 2; ++mb)
#pragma unroll
        for (int nb = 0; nb < 4; ++nb)
#pragma unroll
            for (int q = 0; q < 4; ++q) acc[mb][nb][q] = 0.f;

    int br0 = wn * 32 + (lane & 7) + ((lane >> 4) << 3);
    int ar_base = wm * 32 + (lane & 15);
    int cb = (lane >> 3) & 1;
    int ca = lane >> 4;

#pragma unroll
    for (int ks = 0; ks < 8; ++ks) {
        uint32_t Bh0[4], Bh1[4], Bl0[4], Bl1[4];
        uint32_t Ah[2][4], Al[2][4];
        {
            uint32_t offb0 = swz(br0, ks * 2 + cb);
            uint32_t offb1 = swz(br0 + 16, ks * 2 + cb);
            ldsm_x4(Bh0, sWhi + offb0);
            ldsm_x4(Bl0, sWlo + offb0);
            ldsm_x4(Bh1, sWhi + offb1);
            ldsm_x4(Bl1, sWlo + offb1);
        }
#pragma unroll
        for (int m = 0; m < 2; ++m) {
            uint32_t offa = swz(ar_base + m * 16, ks * 2 + ca);
            ldsm_x4(Ah[m], sPhi + offa);
            ldsm_x4(Al[m], sPlo + offa);
        }
#pragma unroll
        for (int mb = 0; mb < 2; ++mb) {
            mma_bf16(acc[mb][0], Ah[mb], Bh0);
            mma_bf16(acc[mb][0], Al[mb], Bh0);
            mma_bf16(acc[mb][0], Ah[mb], Bl0);
            mma_bf16(acc[mb][1], Ah[mb], Bh0 + 2);
            mma_bf16(acc[mb][1], Al[mb], Bh0 + 2);
            mma_bf16(acc[mb][1], Ah[mb], Bl0 + 2);
            mma_bf16(acc[mb][2], Ah[mb], Bh1);
            mma_bf16(acc[mb][2], Al[mb], Bh1);
            mma_bf16(acc[mb][2], Ah[mb], Bl1);
            mma_bf16(acc[mb][3], Ah[mb], Bh1 + 2);
            mma_bf16(acc[mb][3], Al[mb], Bh1 + 2);
            mma_bf16(acc[mb][3], Ah[mb], Bl1 + 2);
        }
    }
}

// ================= edge kernel: 64-row tiles, 4-stage ring =================
// ctrl: full[st] = ctrl + st*8 (st 0..3); empty[st] = ctrl + 32 + st*8
__global__ __launch_bounds__(WSTHREADS, 1)
void edge_ws_kernel(const float* __restrict__ ah, const float* __restrict__ bh,
                    const float* __restrict__ Wo, float* __restrict__ out,
                    const void* __restrict__ sraw, const void* __restrict__ traw,
                    int E, int nTiles) {
    extern __shared__ __align__(128) char sm[];
    char* Whi = sm;
    char* Wlo = sm + 32768;
    char* Pb  = sm + 65536;                 // 4 stages x (Phi 16K | Plo 16K)
    uint32_t ctrl = smem_u32(sm + 196608);
    uint32_t sWhi = smem_u32(Whi), sWlo = smem_u32(Wlo);
    uint32_t sP = smem_u32(Pb);

    int tid = threadIdx.x;
    int wid = tid >> 5, lane = tid & 31;

    if (tid == 0) {
#pragma unroll
        for (int q = 0; q < 8; ++q) mbar_init(ctrl + q * 8, 1);
    }
    fill_W_split(Whi, Wlo, Wo, tid, WSTHREADS);
    __syncthreads();

    if (wid >= 8) {
        // ===== producer: group g = (wid-8)>>2 takes tiles with it&1==g =====
        int is64 = detect_is64(sraw, lane);
        int pg = (wid - 8) >> 2;          // 0/1
        int wp = (wid - 8) & 3;           // 0..3
        int r0w = wp * 16;                // rows [r0w, r0w+16) of the 64-row tile
        int barid = 4 + pg;
        bool leader = (tid == 256 + pg * 128);
        uint32_t pe[4] = {0, 0, 0, 0};
        int k = 0;                        // group-local tile counter
        for (int it = pg; ; it += 2, ++k) {
            int tile = blockIdx.x * 1;    // computed below
            // global tile for this CTA's it-th iteration:
            // CTA processes tiles blockIdx.x + GRIDX*it
            long long tl = (long long)blockIdx.x + (long long)GRIDX * it;
            if (tl >= nTiles) break;
            tile = (int)tl;
            int st = it & 3;
            char* Phi = Pb + st * 32768;
            char* Plo = Phi + 16384;
            int base = tile * ETILE;

            // prefetch 16 row indices (lanes 0-15: s, 16-31: t)
            int rsel = lane & 15;
            int esel = base + r0w + rsel;
            if (esel >= E) esel = E - 1;
            int idxv;
            if (lane < 16)
                idxv = is64 ? (int)((const long long*)sraw)[esel]
                            : ((const int*)sraw)[esel];
            else
                idxv = is64 ? (int)((const long long*)traw)[esel]
                            : ((const int*)traw)[esel];

            // batch 0 gathers BEFORE the empty wait
            float4 av[4], bv[4], kv[4], vv[4], rv[4];
#pragma unroll
            for (int j = 0; j < 4; ++j) {
                int e = base + r0w + j;
                int ec = (e < E) ? e : (E - 1);
                int si = __shfl_sync(0xffffffffu, idxv, j);
                int vi = __shfl_sync(0xffffffffu, idxv, 16 + j);
                av[j] = __ldcs((const float4*)(ah) + (size_t)ec * 32 + lane);
                bv[j] = __ldcs((const float4*)(bh) + (size_t)ec * 32 + lane);
                kv[j] = *((const float4*)(g_K) + (size_t)si * 32 + lane);
                vv[j] = *((const float4*)(g_V) + (size_t)vi * 32 + lane);
                rv[j] = *((const float4*)(g_R) + (size_t)si * 32 + lane);
            }

            if (k >= 2) { mbar_wait(ctrl + 32 + st * 8, pe[st]); pe[st] ^= 1; }

#pragma unroll
            for (int ib = 0; ib < 4; ++ib) {
#pragma unroll
                for (int j = 0; j < 4; ++j) {
                    int row = r0w + ib * 4 + j;
                    float p0 = rv[j].x * __fdividef(av[j].x + kv[j].x * vv[j].x,
                                                    bv[j].x + kv[j].x + 1e-20f);
                    float p1 = rv[j].y * __fdividef(av[j].y + kv[j].y * vv[j].y,
                                                    bv[j].y + kv[j].y + 1e-20f);
                    float p2 = rv[j].z * __fdividef(av[j].z + kv[j].z * vv[j].z,
                                                    bv[j].z + kv[j].z + 1e-20f);
                    float p3 = rv[j].w * __fdividef(av[j].w + kv[j].w * vv[j].w,
                                                    bv[j].w + kv[j].w + 1e-20f);
                    prod_store_row(Phi, Plo, row, lane, p0, p1, p2, p3);
                }
                if (ib < 3) {
#pragma unroll
                    for (int j = 0; j < 4; ++j) {
                        int i = (ib + 1) * 4 + j;
                        int e = base + r0w + i;
                        int ec = (e < E) ? e : (E - 1);
                        int si = __shfl_sync(0xffffffffu, idxv, i);
                        int vi = __shfl_sync(0xffffffffu, idxv, 16 + i);
                        av[j] = __ldcs((const float4*)(ah) + (size_t)ec * 32 + lane);
                        bv[j] = __ldcs((const float4*)(bh) + (size_t)ec * 32 + lane);
                        kv[j] = *((const float4*)(g_K) + (size_t)si * 32 + lane);
                        vv[j] = *((const float4*)(g_V) + (size_t)vi * 32 + lane);
                        rv[j] = *((const float4*)(g_R) + (size_t)si * 32 + lane);
                    }
                }
            }
            BARSYNC(barid, 128);
            if (leader) mbar_arrive(ctrl + st * 8);   // full[st]
        }
    } else {
        // ===== consumer: all 8 warps consume tiles in order =====
        int wm = wid >> 2, wn = wid & 3;
        int col0 = wn * 32 + (lane & 3) * 8;
        uint32_t pf[4] = {0, 0, 0, 0};
        int it = 0;
        for (long long tl = blockIdx.x; tl < nTiles; tl += GRIDX, ++it) {
            int tile = (int)tl;
            int st = it & 3;
            mbar_wait(ctrl + st * 8, pf[st]); pf[st] ^= 1;
            uint32_t sPhi = sP + st * 32768;
            uint32_t sPlo = sPhi + 16384;

            float acc[2][4][4];
            consumer_gemm32(sPhi, sPlo, sWhi, sWlo, wm, wn, lane, acc);

            BARSYNC(2, 256);
            if (tid == 0) mbar_arrive(ctrl + 32 + st * 8);  // empty[st]

            int base = tile * ETILE;
#pragma unroll
            for (int mb = 0; mb < 2; ++mb) {
                int rA = base + wm * 32 + mb * 16 + (lane >> 2);
                int rB = rA + 8;
                if (rA < E) {
                    float4 fa = make_float4(acc[mb][0][0], acc[mb][0][1],
                                            acc[mb][1][0], acc[mb][1][1]);
                    float4 fb = make_float4(acc[mb][2][0], acc[mb][2][1],
                                            acc[mb][3][0], acc[mb][3][1]);
                    __stcs((float4*)(out + (size_t)rA * CDIM + col0), fa);
                    __stcs((float4*)(out + (size_t)rA * CDIM + col0 + 4), fb);
                }
                if (rB < E) {
                    float4 fc = make_float4(acc[mb][0][2], acc[mb][0][3],
                                            acc[mb][1][2], acc[mb][1][3]);
                    float4 fd = make_float4(acc[mb][2][2], acc[mb][2][3],
                                            acc[mb][3][2], acc[mb][3][3]);
                    __stcs((float4*)(out + (size_t)rB * CDIM + col0), fc);
                    __stcs((float4*)(out + (size_t)rB * CDIM + col0 + 4), fd);
                }
            }
        }
    }
}

// ================= node kernel (R11 verbatim) =================
__global__ __launch_bounds__(WSTHREADS, 1)
void node_ws_kernel(const float* __restrict__ x, const float* __restrict__ prevx,
                    const float* __restrict__ Wk, const float* __restrict__ Wv,
                    const float* __restrict__ Wr,
                    const float* __restrict__ tmk, const float* __restrict__ tmv,
                    const float* __restrict__ tmr, const float* __restrict__ tw,
                    const void* ip, const void* Tp,
                    int N, int nTiles) {
    extern __shared__ __align__(128) char sm[];
    char* Whi = sm;
    char* Wlo = sm + 32768;
    char* Pb  = sm + 65536;
    uint32_t ctrl = smem_u32(sm + 196608);
    uint32_t sWhi = smem_u32(Whi), sWlo = smem_u32(Wlo);
    uint32_t sP = smem_u32(Pb);

    int tid = threadIdx.x;
    int wid = tid >> 5, lane = tid & 31;
    int mat = blockIdx.y;
    const float* W  = (mat == 0) ? Wk  : (mat == 1) ? Wv  : Wr;
    const float* tm = (mat == 0) ? tmk : (mat == 1) ? tmv : tmr;
    float* dstG = (mat == 0) ? g_K : (mat == 1) ? g_V : g_R;

    if (tid == 0) {
        mbar_init(ctrl + 0, 1);
        mbar_init(ctrl + 8, 1);
        mbar_init(ctrl + 16, 1);
        mbar_init(ctrl + 24, 1);
    }
    fill_W_split(Whi, Wlo, W, tid, WSTHREADS);
    __syncthreads();

    if (wid >= 8) {
        int pw = wid - 8;
        float4 tv = *((const float4*)tm + lane);
        uint32_t pe[2] = {0, 0};
        int it = 0;
        for (int tile = blockIdx.x; tile < nTiles; tile += gridDim.x, ++it) {
            int b = it & 1;
            char* Phi = Pb + b * 65536;
            char* Plo = Phi + 32768;
            int base = tile * TILE;

            float4 xv[4], pv[4];
#pragma unroll
            for (int j = 0; j < 4; ++j) {
                int node = base + pw + 8 * j;
                int nc = (node < N) ? node : (N - 1);
                xv[j] = *((const float4*)(x)     + (size_t)nc * 32 + lane);
                pv[j] = *((const float4*)(prevx) + (size_t)nc * 32 + lane);
            }

            if (it >= 2) { mbar_wait(ctrl + 16 + b * 8, pe[b]); pe[b] ^= 1; }
#pragma unroll
            for (int ib = 0; ib < 4; ++ib) {
#pragma unroll
                for (int j = 0; j < 4; ++j) {
                    int i = ib * 4 + j;
                    int row = pw + 8 * i;
                    float p0 = pv[j].x + tv.x * (xv[j].x - pv[j].x);
                    float p1 = pv[j].y + tv.y * (xv[j].y - pv[j].y);
                    float p2 = pv[j].z + tv.z * (xv[j].z - pv[j].z);
                    float p3 = pv[j].w + tv.w * (xv[j].w - pv[j].w);
                    prod_store_row(Phi, Plo, row, lane, p0, p1, p2, p3);
                }
                if (ib < 3) {
#pragma unroll
                    for (int j = 0; j < 4; ++j) {
                        int i = (ib + 1) * 4 + j;
                        int node = base + pw + 8 * i;
                        int nc = (node < N) ? node : (N - 1);
                        xv[j] = *((const float4*)(x)     + (size_t)nc * 32 + lane);
                        pv[j] = *((const float4*)(prevx) + (size_t)nc * 32 + lane);
                    }
                }
            }
            BARSYNC(1, 256);
            if (tid == 256) mbar_arrive(ctrl + b * 8);
        }
    } else {
        int wm = wid >> 2, wn = wid & 3;
        int col0 = wn * 32 + (lane & 3) * 8;
        float wreg[8];
        if (mat == 1) {
            int iv = *(const int*)ip;
            int Tv = *(const int*)Tp;
            float f = -(float)(Tv - iv - 1);
#pragma unroll
            for (int i = 0; i < 8; ++i) wreg[i] = __expf(f * tw[col0 + i]);
        }
        uint32_t pf[2] = {0, 0};
        int it = 0;
        for (int tile = blockIdx.x; tile < nTiles; tile += gridDim.x, ++it) {
            int b = it & 1;
            mbar_wait(ctrl + b * 8, pf[b]); pf[b] ^= 1;
            uint32_t sPhi = sP + b * 65536;
            uint32_t sPlo = sPhi + 32768;

            float acc[4][4][4];
            consumer_gemm(sPhi, sPlo, sWhi, sWlo, wm, wn, lane, acc);

            BARSYNC(2, 256);
            if (tid == 0) mbar_arrive(ctrl + 16 + b * 8);

            int base = tile * TILE;
#pragma unroll
            for (int mb = 0; mb < 4; ++mb) {
#pragma unroll
                for (int hh = 0; hh < 2; ++hh) {
                    int row = base + wm * 64 + mb * 16 + (lane >> 2) + hh * 8;
                    if (row >= N) continue;
                    float v8[8];
                    v8[0] = acc[mb][0][hh * 2];  v8[1] = acc[mb][0][hh * 2 + 1];
                    v8[2] = acc[mb][1][hh * 2];  v8[3] = acc[mb][1][hh * 2 + 1];
                    v8[4] = acc[mb][2][hh * 2];  v8[5] = acc[mb][2][hh * 2 + 1];
                    v8[6] = acc[mb][3][hh * 2];  v8[7] = acc[mb][3][hh * 2 + 1];
                    float o8[8];
                    if (mat == 0) {
#pragma unroll
                        for (int i = 0; i < 8; ++i) o8[i] = __expf(fminf(v8[i], 60.0f));
                    } else if (mat == 1) {
#pragma unroll
                        for (int i = 0; i < 8; ++i) o8[i] = v8[i] * wreg[i];
                    } else {
#pragma unroll
                        for (int i = 0; i < 8; ++i)
                            o8[i] = __fdividef(1.0f, 1.0f + __expf(-v8[i]));
                    }
                    float4 fa = make_float4(o8[0], o8[1], o8[2], o8[3]);
                    float4 fb = make_float4(o8[4], o8[5], o8[6], o8[7]);
                    *(float4*)(dstG + (size_t)row * CDIM + col0)     = fa;
                    *(float4*)(dstG + (size_t)row * CDIM + col0 + 4) = fb;
                }
            }
        }
    }
}

// ---------------- launch ----------------
extern "C" void kernel_launch(void* const* d_in, const int* in_sizes, int n_in,
                              void* d_out, int out_size) {
    const float* x      = (const float*)d_in[0];
    const float* prev_x = (const float*)d_in[1];
    const float* ah     = (const float*)d_in[2];
    const float* bh     = (const float*)d_in[3];
    const float* Wk     = (const float*)d_in[4];
    const float* Wv     = (const float*)d_in[5];
    const float* Wr     = (const float*)d_in[6];
    const float* Wo     = (const float*)d_in[7];
    const float* tmk    = (const float*)d_in[8];
    const float* tmv    = (const float*)d_in[9];
    const float* tmr    = (const float*)d_in[10];
    const float* tw     = (const float*)d_in[11];
    const void*  s      = d_in[12];
    const void*  t      = d_in[13];
    const void*  ip     = d_in[14];
    const void*  Tp     = d_in[15];

    int N = in_sizes[0] / CDIM;
    int E = in_sizes[2] / CDIM;

    cudaFuncSetAttribute(edge_ws_kernel, cudaFuncAttributeMaxDynamicSharedMemorySize, WS_SMEM);
    cudaFuncSetAttribute(node_ws_kernel, cudaFuncAttributeMaxDynamicSharedMemorySize, WS_SMEM);

    int nTilesN = (N + TILE - 1) / TILE;
    dim3 ngrid(49, 3);
    node_ws_kernel<<<ngrid, WSTHREADS, WS_SMEM>>>(x, prev_x, Wk, Wv, Wr,
                                                  tmk, tmv, tmr, tw, ip, Tp,
                                                  N, nTilesN);

    int nTiles = (E + ETILE - 1) / ETILE;
    edge_ws_kernel<<<GRIDX, WSTHREADS, WS_SMEM>>>(ah, bh, Wo, (float*)d_out,
                                                  s, t, E, nTiles);
}

// round 15
// speedup vs baseline: 1.0854x; 1.0854x over previous
#include <cuda_runtime.h>
#include <cstdint>

// ---------------- problem constants ----------------
#define CDIM 128
#define MAXN 25600
#define MAXE 404000
#define TILE 128
#define WSTHREADS 512       // 8 consumer + 8 producer warps
#define GRIDX 148

// ---------------- device scratch ----------------
__device__ float g_K[(size_t)MAXN * CDIM];
__device__ float g_V[(size_t)MAXN * CDIM];
__device__ float g_R[(size_t)MAXN * CDIM];

// ---------------- helpers ----------------
__device__ __forceinline__ uint32_t smem_u32(const void* p) {
    return (uint32_t)__cvta_generic_to_shared(p);
}

// swizzled byte offset within a (rows x 256B) tile (16B chunks)
__device__ __forceinline__ uint32_t swz(int row, int chunk) {
    return (uint32_t)(row * 256) + (uint32_t)(((chunk ^ (row & 7)) << 4));
}

// pack two floats -> bf16x2 (lo=a, hi=b) + residual
__device__ __forceinline__ void split2(float a, float b, uint32_t& h, uint32_t& l) {
    asm("cvt.rn.bf16x2.f32 %0, %1, %2;" : "=r"(h) : "f"(b), "f"(a));
    float fa = __uint_as_float(h << 16);
    float fb = __uint_as_float(h & 0xFFFF0000u);
    float ra = a - fa, rb = b - fb;
    asm("cvt.rn.bf16x2.f32 %0, %1, %2;" : "=r"(l) : "f"(rb), "f"(ra));
}

// Fill W tiles with COLUMN PERMUTATION (see R11): thread t of consumer warp wn
// accumulates 8 consecutive output columns col0 = wn*32 + 8t.
__device__ __forceinline__ void fill_W_split(char* Whi, char* Wlo,
                                             const float* __restrict__ W,
                                             int tid, int nthreads) {
    for (int idx = tid; idx < 128 * 16; idx += nthreads) {
        int j = idx >> 4, ci = idx & 15;   // j = DEST smem row
        int w32 = j & ~31;
        int r   = j & 31;
        int nb  = r >> 3;
        int rho = r & 7;
        int c = w32 + ((rho >> 1) << 3) + (nb << 1) + (rho & 1);  // source W col
        const float4* w4 = (const float4*)(W + (size_t)c * CDIM + ci * 8);
        float4 f0 = w4[0], f1 = w4[1];
        uint4 h, l;
        split2(f0.x, f0.y, h.x, l.x);
        split2(f0.z, f0.w, h.y, l.y);
        split2(f1.x, f1.y, h.z, l.z);
        split2(f1.z, f1.w, h.w, l.w);
        uint32_t off = swz(j, ci);
        *(uint4*)(Whi + off) = h;
        *(uint4*)(Wlo + off) = l;
    }
}

__device__ __forceinline__ void ldsm_x4(uint32_t* r, uint32_t addr) {
    asm volatile("ldmatrix.sync.aligned.m8n8.x4.shared.b16 {%0,%1,%2,%3}, [%4];"
                 : "=r"(r[0]), "=r"(r[1]), "=r"(r[2]), "=r"(r[3]) : "r"(addr));
}

__device__ __forceinline__ void mma_bf16(float* d, const uint32_t* a, const uint32_t* b) {
    asm volatile(
        "mma.sync.aligned.m16n8k16.row.col.f32.bf16.bf16.f32 "
        "{%0,%1,%2,%3}, {%4,%5,%6,%7}, {%8,%9}, {%0,%1,%2,%3};"
        : "+f"(d[0]), "+f"(d[1]), "+f"(d[2]), "+f"(d[3])
        : "r"(a[0]), "r"(a[1]), "r"(a[2]), "r"(a[3]), "r"(b[0]), "r"(b[1]));
}

__device__ __forceinline__ void mbar_init(uint32_t mbar, uint32_t cnt) {
    asm volatile("mbarrier.init.shared.b64 [%0], %1;" :: "r"(mbar), "r"(cnt) : "memory");
}
__device__ __forceinline__ void mbar_arrive(uint32_t mbar) {
    asm volatile("mbarrier.arrive.release.cta.shared::cta.b64 _, [%0];"
                 :: "r"(mbar) : "memory");
}
__device__ __forceinline__ void mbar_wait(uint32_t mbar, uint32_t parity) {
    asm volatile(
        "{\n\t.reg .pred P;\n"
        "W_%=:\n\t"
        "mbarrier.try_wait.parity.acquire.cta.shared::cta.b64 P, [%0], %1, 0x989680;\n\t"
        "@P bra.uni D_%=;\n\t"
        "bra.uni W_%=;\n"
        "D_%=:\n\t}"
        :: "r"(mbar), "r"(parity) : "memory");
}

#define BARSYNC(id, n) asm volatile("bar.sync %0, %1;" :: "r"(id), "r"(n) : "memory")

// smem: Whi 32K | Wlo 32K | Pbuf0 64K | Pbuf1 64K | ctrl
#define WS_SMEM (196608 + 128)

// detect int64 indices: odd 32-bit words of first 64 entries are all zero
__device__ __forceinline__ int detect_is64(const void* sraw, int lane) {
    const int* w = (const int*)sraw;
    int v = w[lane * 4 + 1] | w[lane * 4 + 3];
    return __any_sync(0xffffffffu, v != 0) ? 0 : 1;
}

// ---------------- producer row store: lane l owns channels [4l, 4l+4) ----------------
__device__ __forceinline__ void prod_store_row(char* Phi, char* Plo, int row, int lane,
                                               float p0, float p1, float p2, float p3) {
    uint32_t h0, l0, h1, l1;
    split2(p0, p1, h0, l0);
    split2(p2, p3, h1, l1);
    uint32_t off = swz(row, lane >> 1) + (lane & 1) * 8;
    uint2 h; h.x = h0; h.y = h1;
    uint2 l; l.x = l0; l.y = l1;
    *(uint2*)(Phi + off) = h;
    *(uint2*)(Plo + off) = l;
}

// ---------------- consumer GEMM core (8 warps, 64x32 warp tile) ----------------
__device__ __forceinline__ void consumer_gemm(uint32_t sPhi, uint32_t sPlo,
                                              uint32_t sWhi, uint32_t sWlo,
                                              int wm, int wn, int lane,
                                              float acc[4][4][4]) {
#pragma unroll
    for (int mb = 0; mb < 4; ++mb)
#pragma unroll
        for (int nb = 0; nb < 4; ++nb)
#pragma unroll
            for (int q = 0; q < 4; ++q) acc[mb][nb][q] = 0.f;

    int br0 = wn * 32 + (lane & 7) + ((lane >> 4) << 3);
    int ar_base = wm * 64 + (lane & 15);
    int cb = (lane >> 3) & 1;
    int ca = lane >> 4;

#pragma unroll
    for (int ks = 0; ks < 8; ++ks) {
        uint32_t Bh0[4], Bh1[4], Bl0[4], Bl1[4];
        uint32_t Ah[4][4], Al[4][4];
        {
            uint32_t offb0 = swz(br0, ks * 2 + cb);
            uint32_t offb1 = swz(br0 + 16, ks * 2 + cb);
            ldsm_x4(Bh0, sWhi + offb0);
            ldsm_x4(Bl0, sWlo + offb0);
            ldsm_x4(Bh1, sWhi + offb1);
            ldsm_x4(Bl1, sWlo + offb1);
        }
#pragma unroll
        for (int m = 0; m < 4; ++m) {
            uint32_t offa = swz(ar_base + m * 16, ks * 2 + ca);
            ldsm_x4(Ah[m], sPhi + offa);
            ldsm_x4(Al[m], sPlo + offa);
        }
#pragma unroll
        for (int mb = 0; mb < 4; ++mb) {
            mma_bf16(acc[mb][0], Ah[mb], Bh0);
            mma_bf16(acc[mb][0], Al[mb], Bh0);
            mma_bf16(acc[mb][0], Ah[mb], Bl0);
            mma_bf16(acc[mb][1], Ah[mb], Bh0 + 2);
            mma_bf16(acc[mb][1], Al[mb], Bh0 + 2);
            mma_bf16(acc[mb][1], Ah[mb], Bl0 + 2);
            mma_bf16(acc[mb][2], Ah[mb], Bh1);
            mma_bf16(acc[mb][2], Al[mb], Bh1);
            mma_bf16(acc[mb][2], Ah[mb], Bl1);
            mma_bf16(acc[mb][3], Ah[mb], Bh1 + 2);
            mma_bf16(acc[mb][3], Al[mb], Bh1 + 2);
            mma_bf16(acc[mb][3], Ah[mb], Bl1 + 2);
        }
    }
}

// ================= edge kernel: half-tile pipelined, per-warp arrives =================
// ctrl: full[b][h] = ctrl + (b*2+h)*8 (count 4) ; empty[b][h] = ctrl + 32 + (b*2+h)*8 (count 4)
__global__ __launch_bounds__(WSTHREADS, 1)
void edge_ws_kernel(const float* __restrict__ ah, const float* __restrict__ bh,
                    const float* __restrict__ Wo, float* __restrict__ out,
                    const void* __restrict__ sraw, const void* __restrict__ traw,
                    int E, int nTiles) {
    extern __shared__ __align__(128) char sm[];
    char* Whi = sm;
    char* Wlo = sm + 32768;
    char* Pb  = sm + 65536;
    uint32_t ctrl = smem_u32(sm + 196608);
    uint32_t sWhi = smem_u32(Whi), sWlo = smem_u32(Wlo);
    uint32_t sP = smem_u32(Pb);

    int tid = threadIdx.x;
    int wid = tid >> 5, lane = tid & 31;

    if (tid == 0) {
#pragma unroll
        for (int q = 0; q < 8; ++q) mbar_init(ctrl + q * 8, 4);
    }
    fill_W_split(Whi, Wlo, Wo, tid, WSTHREADS);
    __syncthreads();

    if (wid >= 8) {
        // ============ producer: warp pw owns rows [pw*16, pw*16+16) ============
        int is64 = detect_is64(sraw, lane);
        int pw = wid - 8;                 // 0..7
        int h  = pw >> 2;                 // half 0/1
        int r0w = pw * 16;
        uint32_t pe[2] = {0, 0};
        int it = 0;
        for (int tile = blockIdx.x; tile < nTiles; tile += gridDim.x, ++it) {
            int b = it & 1;
            char* Phi = Pb + b * 65536;
            char* Plo = Phi + 32768;
            int base = tile * TILE;

            // prefetch all 16 row indices in one coalesced load
            int rsel = lane & 15;
            int esel = base + r0w + rsel;
            if (esel >= E) esel = E - 1;
            int idxv;
            if (lane < 16)
                idxv = is64 ? (int)((const long long*)sraw)[esel]
                            : ((const int*)sraw)[esel];
            else
                idxv = is64 ? (int)((const long long*)traw)[esel]
                            : ((const int*)traw)[esel];

            // batch 0 gathers BEFORE the empty wait (registers only)
            float4 av[4], bv[4], kv[4], vv[4], rv[4];
#pragma unroll
            for (int j = 0; j < 4; ++j) {
                int e = base + r0w + j;
                int ec = (e < E) ? e : (E - 1);
                int si = __shfl_sync(0xffffffffu, idxv, j);
                int vi = __shfl_sync(0xffffffffu, idxv, 16 + j);
                av[j] = __ldcs((const float4*)(ah) + (size_t)ec * 32 + lane);
                bv[j] = __ldcs((const float4*)(bh) + (size_t)ec * 32 + lane);
                kv[j] = *((const float4*)(g_K) + (size_t)si * 32 + lane);
                vv[j] = *((const float4*)(g_V) + (size_t)vi * 32 + lane);
                rv[j] = *((const float4*)(g_R) + (size_t)si * 32 + lane);
            }

            if (it >= 2) { mbar_wait(ctrl + 32 + (b * 2 + h) * 8, pe[b]); pe[b] ^= 1; }

#pragma unroll
            for (int ib = 0; ib < 4; ++ib) {
#pragma unroll
                for (int j = 0; j < 4; ++j) {
                    int row = r0w + ib * 4 + j;
                    float p0 = rv[j].x * __fdividef(av[j].x + kv[j].x * vv[j].x,
                                                    bv[j].x + kv[j].x + 1e-20f);
                    float p1 = rv[j].y * __fdividef(av[j].y + kv[j].y * vv[j].y,
                                                    bv[j].y + kv[j].y + 1e-20f);
                    float p2 = rv[j].z * __fdividef(av[j].z + kv[j].z * vv[j].z,
                                                    bv[j].z + kv[j].z + 1e-20f);
                    float p3 = rv[j].w * __fdividef(av[j].w + kv[j].w * vv[j].w,
                                                    bv[j].w + kv[j].w + 1e-20f);
                    prod_store_row(Phi, Plo, row, lane, p0, p1, p2, p3);
                }
                if (ib < 3) {
#pragma unroll
                    for (int j = 0; j < 4; ++j) {
                        int i = (ib + 1) * 4 + j;
                        int e = base + r0w + i;
                        int ec = (e < E) ? e : (E - 1);
                        int si = __shfl_sync(0xffffffffu, idxv, i);
                        int vi = __shfl_sync(0xffffffffu, idxv, 16 + i);
                        av[j] = __ldcs((const float4*)(ah) + (size_t)ec * 32 + lane);
                        bv[j] = __ldcs((const float4*)(bh) + (size_t)ec * 32 + lane);
                        kv[j] = *((const float4*)(g_K) + (size_t)si * 32 + lane);
                        vv[j] = *((const float4*)(g_V) + (size_t)vi * 32 + lane);
                        rv[j] = *((const float4*)(g_R) + (size_t)si * 32 + lane);
                    }
                }
            }
            // per-warp arrive: syncwarp fence orders all lanes' STS before the
            // elected lane's release-arrive; count-4 mbar completes when all
            // 4 warps of this half have arrived.
            __syncwarp();
            if (lane == 0) mbar_arrive(ctrl + (b * 2 + h) * 8);   // full[b][h]
        }
    } else {
        // ================= consumer: wm group handles half wm =================
        int wm = wid >> 2, wn = wid & 3;
        int col0 = wn * 32 + (lane & 3) * 8;   // 8 consecutive output cols
        uint32_t pf[2] = {0, 0};
        int it = 0;
        for (int tile = blockIdx.x; tile < nTiles; tile += gridDim.x, ++it) {
            int b = it & 1;
            mbar_wait(ctrl + (b * 2 + wm) * 8, pf[b]); pf[b] ^= 1;
            uint32_t sPhi = sP + b * 65536;
            uint32_t sPlo = sPhi + 32768;

            float acc[4][4][4];
            consumer_gemm(sPhi, sPlo, sWhi, sWlo, wm, wn, lane, acc);

            // this warp's reads of buffer b are complete; release it
            __syncwarp();
            if (lane == 0) mbar_arrive(ctrl + 32 + (b * 2 + wm) * 8);  // empty[b][wm]

            int base = tile * TILE;
#pragma unroll
            for (int mb = 0; mb < 4; ++mb) {
                int rA = base + wm * 64 + mb * 16 + (lane >> 2);
                int rB = rA + 8;
                if (rA < E) {
                    float4 fa = make_float4(acc[mb][0][0], acc[mb][0][1],
                                            acc[mb][1][0], acc[mb][1][1]);
                    float4 fb = make_float4(acc[mb][2][0], acc[mb][2][1],
                                            acc[mb][3][0], acc[mb][3][1]);
                    __stcs((float4*)(out + (size_t)rA * CDIM + col0), fa);
                    __stcs((float4*)(out + (size_t)rA * CDIM + col0 + 4), fb);
                }
                if (rB < E) {
                    float4 fc = make_float4(acc[mb][0][2], acc[mb][0][3],
                                            acc[mb][1][2], acc[mb][1][3]);
                    float4 fd = make_float4(acc[mb][2][2], acc[mb][2][3],
                                            acc[mb][3][2], acc[mb][3][3]);
                    __stcs((float4*)(out + (size_t)rB * CDIM + col0), fc);
                    __stcs((float4*)(out + (size_t)rB * CDIM + col0 + 4), fd);
                }
            }
        }
    }
}

// ================= node kernel (R11 verbatim) =================
__global__ __launch_bounds__(WSTHREADS, 1)
void node_ws_kernel(const float* __restrict__ x, const float* __restrict__ prevx,
                    const float* __restrict__ Wk, const float* __restrict__ Wv,
                    const float* __restrict__ Wr,
                    const float* __restrict__ tmk, const float* __restrict__ tmv,
                    const float* __restrict__ tmr, const float* __restrict__ tw,
                    const void* ip, const void* Tp,
                    int N, int nTiles) {
    extern __shared__ __align__(128) char sm[];
    char* Whi = sm;
    char* Wlo = sm + 32768;
    char* Pb  = sm + 65536;
    uint32_t ctrl = smem_u32(sm + 196608);
    uint32_t sWhi = smem_u32(Whi), sWlo = smem_u32(Wlo);
    uint32_t sP = smem_u32(Pb);

    int tid = threadIdx.x;
    int wid = tid >> 5, lane = tid & 31;
    int mat = blockIdx.y;
    const float* W  = (mat == 0) ? Wk  : (mat == 1) ? Wv  : Wr;
    const float* tm = (mat == 0) ? tmk : (mat == 1) ? tmv : tmr;
    float* dstG = (mat == 0) ? g_K : (mat == 1) ? g_V : g_R;

    if (tid == 0) {
        mbar_init(ctrl + 0, 1);
        mbar_init(ctrl + 8, 1);
        mbar_init(ctrl + 16, 1);
        mbar_init(ctrl + 24, 1);
    }
    fill_W_split(Whi, Wlo, W, tid, WSTHREADS);
    __syncthreads();

    if (wid >= 8) {
        int pw = wid - 8;
        float4 tv = *((const float4*)tm + lane);
        uint32_t pe[2] = {0, 0};
        int it = 0;
        for (int tile = blockIdx.x; tile < nTiles; tile += gridDim.x, ++it) {
            int b = it & 1;
            char* Phi = Pb + b * 65536;
            char* Plo = Phi + 32768;
            int base = tile * TILE;

            float4 xv[4], pv[4];
#pragma unroll
            for (int j = 0; j < 4; ++j) {
                int node = base + pw + 8 * j;
                int nc = (node < N) ? node : (N - 1);
                xv[j] = *((const float4*)(x)     + (size_t)nc * 32 + lane);
                pv[j] = *((const float4*)(prevx) + (size_t)nc * 32 + lane);
            }

            if (it >= 2) { mbar_wait(ctrl + 16 + b * 8, pe[b]); pe[b] ^= 1; }
#pragma unroll
            for (int ib = 0; ib < 4; ++ib) {
#pragma unroll
                for (int j = 0; j < 4; ++j) {
                    int i = ib * 4 + j;
                    int row = pw + 8 * i;
                    float p0 = pv[j].x + tv.x * (xv[j].x - pv[j].x);
                    float p1 = pv[j].y + tv.y * (xv[j].y - pv[j].y);
                    float p2 = pv[j].z + tv.z * (xv[j].z - pv[j].z);
                    float p3 = pv[j].w + tv.w * (xv[j].w - pv[j].w);
                    prod_store_row(Phi, Plo, row, lane, p0, p1, p2, p3);
                }
                if (ib < 3) {
#pragma unroll
                    for (int j = 0; j < 4; ++j) {
                        int i = (ib + 1) * 4 + j;
                        int node = base + pw + 8 * i;
                        int nc = (node < N) ? node : (N - 1);
                        xv[j] = *((const float4*)(x)     + (size_t)nc * 32 + lane);
                        pv[j] = *((const float4*)(prevx) + (size_t)nc * 32 + lane);
                    }
                }
            }
            BARSYNC(1, 256);
            if (tid == 256) mbar_arrive(ctrl + b * 8);
        }
    } else {
        int wm = wid >> 2, wn = wid & 3;
        int col0 = wn * 32 + (lane & 3) * 8;
        float wreg[8];
        if (mat == 1) {
            int iv = *(const int*)ip;
            int Tv = *(const int*)Tp;
            float f = -(float)(Tv - iv - 1);
#pragma unroll
            for (int i = 0; i < 8; ++i) wreg[i] = __expf(f * tw[col0 + i]);
        }
        uint32_t pf[2] = {0, 0};
        int it = 0;
        for (int tile = blockIdx.x; tile < nTiles; tile += gridDim.x, ++it) {
            int b = it & 1;
            mbar_wait(ctrl + b * 8, pf[b]); pf[b] ^= 1;
            uint32_t sPhi = sP + b * 65536;
            uint32_t sPlo = sPhi + 32768;

            float acc[4][4][4];
            consumer_gemm(sPhi, sPlo, sWhi, sWlo, wm, wn, lane, acc);

            BARSYNC(2, 256);
            if (tid == 0) mbar_arrive(ctrl + 16 + b * 8);

            int base = tile * TILE;
#pragma unroll
            for (int mb = 0; mb < 4; ++mb) {
#pragma unroll
                for (int hh = 0; hh < 2; ++hh) {
                    int row = base + wm * 64 + mb * 16 + (lane >> 2) + hh * 8;
                    if (row >= N) continue;
                    float v8[8];
                    v8[0] = acc[mb][0][hh * 2];  v8[1] = acc[mb][0][hh * 2 + 1];
                    v8[2] = acc[mb][1][hh * 2];  v8[3] = acc[mb][1][hh * 2 + 1];
                    v8[4] = acc[mb][2][hh * 2];  v8[5] = acc[mb][2][hh * 2 + 1];
                    v8[6] = acc[mb][3][hh * 2];  v8[7] = acc[mb][3][hh * 2 + 1];
                    float o8[8];
                    if (mat == 0) {
#pragma unroll
                        for (int i = 0; i < 8; ++i) o8[i] = __expf(fminf(v8[i], 60.0f));
                    } else if (mat == 1) {
#pragma unroll
                        for (int i = 0; i < 8; ++i) o8[i] = v8[i] * wreg[i];
                    } else {
#pragma unroll
                        for (int i = 0; i < 8; ++i)
                            o8[i] = __fdividef(1.0f, 1.0f + __expf(-v8[i]));
                    }
                    float4 fa = make_float4(o8[0], o8[1], o8[2], o8[3]);
                    float4 fb = make_float4(o8[4], o8[5], o8[6], o8[7]);
                    *(float4*)(dstG + (size_t)row * CDIM + col0)     = fa;
                    *(float4*)(dstG + (size_t)row * CDIM + col0 + 4) = fb;
                }
            }
        }
    }
}

// ---------------- launch ----------------
extern "C" void kernel_launch(void* const* d_in, const int* in_sizes, int n_in,
                              void* d_out, int out_size) {
    const float* x      = (const float*)d_in[0];
    const float* prev_x = (const float*)d_in[1];
    const float* ah     = (const float*)d_in[2];
    const float* bh     = (const float*)d_in[3];
    const float* Wk     = (const float*)d_in[4];
    const float* Wv     = (const float*)d_in[5];
    const float* Wr     = (const float*)d_in[6];
    const float* Wo     = (const float*)d_in[7];
    const float* tmk    = (const float*)d_in[8];
    const float* tmv    = (const float*)d_in[9];
    const float* tmr    = (const float*)d_in[10];
    const float* tw     = (const float*)d_in[11];
    const void*  s      = d_in[12];
    const void*  t      = d_in[13];
    const void*  ip     = d_in[14];
    const void*  Tp     = d_in[15];

    int N = in_sizes[0] / CDIM;
    int E = in_sizes[2] / CDIM;

    cudaFuncSetAttribute(edge_ws_kernel, cudaFuncAttributeMaxDynamicSharedMemorySize, WS_SMEM);
    cudaFuncSetAttribute(node_ws_kernel, cudaFuncAttributeMaxDynamicSharedMemorySize, WS_SMEM);

    int nTilesN = (N + TILE - 1) / TILE;
    dim3 ngrid(49, 3);
    node_ws_kernel<<<ngrid, WSTHREADS, WS_SMEM>>>(x, prev_x, Wk, Wv, Wr,
                                                  tmk, tmv, tmr, tw, ip, Tp,
                                                  N, nTilesN);

    int nTiles = (E + TILE - 1) / TILE;
    edge_ws_kernel<<<GRIDX, WSTHREADS, WS_SMEM>>>(ah, bh, Wo, (float*)d_out,
                                                  s, t, E, nTiles);
}

// round 16
// speedup vs baseline: 1.1001x; 1.0135x over previous
#include <cuda_runtime.h>
#include <cstdint>

// ---------------- problem constants ----------------
#define CDIM 128
#define MAXN 25600
#define MAXE 404000
#define TILE 128
#define WSTHREADS 512       // 8 consumer + 8 producer warps
#define GRIDX 148

// ---------------- device scratch ----------------
__device__ float g_K[(size_t)MAXN * CDIM];
__device__ float g_V[(size_t)MAXN * CDIM];
__device__ float g_R[(size_t)MAXN * CDIM];

// ---------------- helpers ----------------
__device__ __forceinline__ uint32_t smem_u32(const void* p) {
    return (uint32_t)__cvta_generic_to_shared(p);
}

// swizzled byte offset within a (rows x 256B) tile (16B chunks)
__device__ __forceinline__ uint32_t swz(int row, int chunk) {
    return (uint32_t)(row * 256) + (uint32_t)(((chunk ^ (row & 7)) << 4));
}

// pack two floats -> bf16x2 (lo=a, hi=b) + residual
__device__ __forceinline__ void split2(float a, float b, uint32_t& h, uint32_t& l) {
    asm("cvt.rn.bf16x2.f32 %0, %1, %2;" : "=r"(h) : "f"(b), "f"(a));
    float fa = __uint_as_float(h << 16);
    float fb = __uint_as_float(h & 0xFFFF0000u);
    float ra = a - fa, rb = b - fb;
    asm("cvt.rn.bf16x2.f32 %0, %1, %2;" : "=r"(l) : "f"(rb), "f"(ra));
}

// Fill W tiles with COLUMN PERMUTATION (see R11): thread t of consumer warp wn
// accumulates 8 consecutive output columns col0 = wn*32 + 8t.
__device__ __forceinline__ void fill_W_split(char* Whi, char* Wlo,
                                             const float* __restrict__ W,
                                             int tid, int nthreads) {
    for (int idx = tid; idx < 128 * 16; idx += nthreads) {
        int j = idx >> 4, ci = idx & 15;   // j = DEST smem row
        int w32 = j & ~31;
        int r   = j & 31;
        int nb  = r >> 3;
        int rho = r & 7;
        int c = w32 + ((rho >> 1) << 3) + (nb << 1) + (rho & 1);  // source W col
        const float4* w4 = (const float4*)(W + (size_t)c * CDIM + ci * 8);
        float4 f0 = w4[0], f1 = w4[1];
        uint4 h, l;
        split2(f0.x, f0.y, h.x, l.x);
        split2(f0.z, f0.w, h.y, l.y);
        split2(f1.x, f1.y, h.z, l.z);
        split2(f1.z, f1.w, h.w, l.w);
        uint32_t off = swz(j, ci);
        *(uint4*)(Whi + off) = h;
        *(uint4*)(Wlo + off) = l;
    }
}

__device__ __forceinline__ void ldsm_x4(uint32_t* r, uint32_t addr) {
    asm volatile("ldmatrix.sync.aligned.m8n8.x4.shared.b16 {%0,%1,%2,%3}, [%4];"
                 : "=r"(r[0]), "=r"(r[1]), "=r"(r[2]), "=r"(r[3]) : "r"(addr));
}

__device__ __forceinline__ void mma_bf16(float* d, const uint32_t* a, const uint32_t* b) {
    asm volatile(
        "mma.sync.aligned.m16n8k16.row.col.f32.bf16.bf16.f32 "
        "{%0,%1,%2,%3}, {%4,%5,%6,%7}, {%8,%9}, {%0,%1,%2,%3};"
        : "+f"(d[0]), "+f"(d[1]), "+f"(d[2]), "+f"(d[3])
        : "r"(a[0]), "r"(a[1]), "r"(a[2]), "r"(a[3]), "r"(b[0]), "r"(b[1]));
}

__device__ __forceinline__ void mbar_init(uint32_t mbar, uint32_t cnt) {
    asm volatile("mbarrier.init.shared.b64 [%0], %1;" :: "r"(mbar), "r"(cnt) : "memory");
}
__device__ __forceinline__ void mbar_arrive(uint32_t mbar) {
    asm volatile("mbarrier.arrive.release.cta.shared::cta.b64 _, [%0];"
                 :: "r"(mbar) : "memory");
}
__device__ __forceinline__ void mbar_wait(uint32_t mbar, uint32_t parity) {
    asm volatile(
        "{\n\t.reg .pred P;\n"
        "W_%=:\n\t"
        "mbarrier.try_wait.parity.acquire.cta.shared::cta.b64 P, [%0], %1, 0x989680;\n\t"
        "@P bra.uni D_%=;\n\t"
        "bra.uni W_%=;\n"
        "D_%=:\n\t}"
        :: "r"(mbar), "r"(parity) : "memory");
}

// smem: Whi 32K | Wlo 32K | Pbuf0 64K | Pbuf1 64K | ctrl
#define WS_SMEM (196608 + 128)

// detect int64 indices: odd 32-bit words of first 64 entries are all zero
__device__ __forceinline__ int detect_is64(const void* sraw, int lane) {
    const int* w = (const int*)sraw;
    int v = w[lane * 4 + 1] | w[lane * 4 + 3];
    return __any_sync(0xffffffffu, v != 0) ? 0 : 1;
}

// ---------------- producer row store: lane l owns channels [4l, 4l+4) ----------------
__device__ __forceinline__ void prod_store_row(char* Phi, char* Plo, int row, int lane,
                                               float p0, float p1, float p2, float p3) {
    uint32_t h0, l0, h1, l1;
    split2(p0, p1, h0, l0);
    split2(p2, p3, h1, l1);
    uint32_t off = swz(row, lane >> 1) + (lane & 1) * 8;
    uint2 h; h.x = h0; h.y = h1;
    uint2 l; l.x = l0; l.y = l1;
    *(uint2*)(Phi + off) = h;
    *(uint2*)(Plo + off) = l;
}

// ---------------- consumer GEMM core (8 warps, 64x32 warp tile) ----------------
__device__ __forceinline__ void consumer_gemm(uint32_t sPhi, uint32_t sPlo,
                                              uint32_t sWhi, uint32_t sWlo,
                                              int wm, int wn, int lane,
                                              float acc[4][4][4]) {
#pragma unroll
    for (int mb = 0; mb < 4; ++mb)
#pragma unroll
        for (int nb = 0; nb < 4; ++nb)
#pragma unroll
            for (int q = 0; q < 4; ++q) acc[mb][nb][q] = 0.f;

    int br0 = wn * 32 + (lane & 7) + ((lane >> 4) << 3);
    int ar_base = wm * 64 + (lane & 15);
    int cb = (lane >> 3) & 1;
    int ca = lane >> 4;

#pragma unroll
    for (int ks = 0; ks < 8; ++ks) {
        uint32_t Bh0[4], Bh1[4], Bl0[4], Bl1[4];
        uint32_t Ah[4][4], Al[4][4];
        {
            uint32_t offb0 = swz(br0, ks * 2 + cb);
            uint32_t offb1 = swz(br0 + 16, ks * 2 + cb);
            ldsm_x4(Bh0, sWhi + offb0);
            ldsm_x4(Bl0, sWlo + offb0);
            ldsm_x4(Bh1, sWhi + offb1);
            ldsm_x4(Bl1, sWlo + offb1);
        }
#pragma unroll
        for (int m = 0; m < 4; ++m) {
            uint32_t offa = swz(ar_base + m * 16, ks * 2 + ca);
            ldsm_x4(Ah[m], sPhi + offa);
            ldsm_x4(Al[m], sPlo + offa);
        }
#pragma unroll
        for (int mb = 0; mb < 4; ++mb) {
            mma_bf16(acc[mb][0], Ah[mb], Bh0);
            mma_bf16(acc[mb][0], Al[mb], Bh0);
            mma_bf16(acc[mb][0], Ah[mb], Bl0);
            mma_bf16(acc[mb][1], Ah[mb], Bh0 + 2);
            mma_bf16(acc[mb][1], Al[mb], Bh0 + 2);
            mma_bf16(acc[mb][1], Ah[mb], Bl0 + 2);
            mma_bf16(acc[mb][2], Ah[mb], Bh1);
            mma_bf16(acc[mb][2], Al[mb], Bh1);
            mma_bf16(acc[mb][2], Ah[mb], Bl1);
            mma_bf16(acc[mb][3], Ah[mb], Bh1 + 2);
            mma_bf16(acc[mb][3], Al[mb], Bh1 + 2);
            mma_bf16(acc[mb][3], Ah[mb], Bl1 + 2);
        }
    }
}

// ================= edge kernel (R15 verbatim: per-warp arrives) =================
// ctrl: full[b][h] = ctrl + (b*2+h)*8 (count 4) ; empty[b][h] = ctrl + 32 + (b*2+h)*8 (count 4)
__global__ __launch_bounds__(WSTHREADS, 1)
void edge_ws_kernel(const float* __restrict__ ah, const float* __restrict__ bh,
                    const float* __restrict__ Wo, float* __restrict__ out,
                    const void* __restrict__ sraw, const void* __restrict__ traw,
                    int E, int nTiles) {
    extern __shared__ __align__(128) char sm[];
    char* Whi = sm;
    char* Wlo = sm + 32768;
    char* Pb  = sm + 65536;
    uint32_t ctrl = smem_u32(sm + 196608);
    uint32_t sWhi = smem_u32(Whi), sWlo = smem_u32(Wlo);
    uint32_t sP = smem_u32(Pb);

    int tid = threadIdx.x;
    int wid = tid >> 5, lane = tid & 31;

    if (tid == 0) {
#pragma unroll
        for (int q = 0; q < 8; ++q) mbar_init(ctrl + q * 8, 4);
    }
    fill_W_split(Whi, Wlo, Wo, tid, WSTHREADS);
    __syncthreads();

    if (wid >= 8) {
        // ============ producer: warp pw owns rows [pw*16, pw*16+16) ============
        int is64 = detect_is64(sraw, lane);
        int pw = wid - 8;                 // 0..7
        int h  = pw >> 2;                 // half 0/1
        int r0w = pw * 16;
        uint32_t pe[2] = {0, 0};
        int it = 0;
        for (int tile = blockIdx.x; tile < nTiles; tile += gridDim.x, ++it) {
            int b = it & 1;
            char* Phi = Pb + b * 65536;
            char* Plo = Phi + 32768;
            int base = tile * TILE;

            // prefetch all 16 row indices in one coalesced load
            int rsel = lane & 15;
            int esel = base + r0w + rsel;
            if (esel >= E) esel = E - 1;
            int idxv;
            if (lane < 16)
                idxv = is64 ? (int)((const long long*)sraw)[esel]
                            : ((const int*)sraw)[esel];
            else
                idxv = is64 ? (int)((const long long*)traw)[esel]
                            : ((const int*)traw)[esel];

            // batch 0 gathers BEFORE the empty wait (registers only)
            float4 av[4], bv[4], kv[4], vv[4], rv[4];
#pragma unroll
            for (int j = 0; j < 4; ++j) {
                int e = base + r0w + j;
                int ec = (e < E) ? e : (E - 1);
                int si = __shfl_sync(0xffffffffu, idxv, j);
                int vi = __shfl_sync(0xffffffffu, idxv, 16 + j);
                av[j] = __ldcs((const float4*)(ah) + (size_t)ec * 32 + lane);
                bv[j] = __ldcs((const float4*)(bh) + (size_t)ec * 32 + lane);
                kv[j] = *((const float4*)(g_K) + (size_t)si * 32 + lane);
                vv[j] = *((const float4*)(g_V) + (size_t)vi * 32 + lane);
                rv[j] = *((const float4*)(g_R) + (size_t)si * 32 + lane);
            }

            if (it >= 2) { mbar_wait(ctrl + 32 + (b * 2 + h) * 8, pe[b]); pe[b] ^= 1; }

#pragma unroll
            for (int ib = 0; ib < 4; ++ib) {
#pragma unroll
                for (int j = 0; j < 4; ++j) {
                    int row = r0w + ib * 4 + j;
                    float p0 = rv[j].x * __fdividef(av[j].x + kv[j].x * vv[j].x,
                                                    bv[j].x + kv[j].x + 1e-20f);
                    float p1 = rv[j].y * __fdividef(av[j].y + kv[j].y * vv[j].y,
                                                    bv[j].y + kv[j].y + 1e-20f);
                    float p2 = rv[j].z * __fdividef(av[j].z + kv[j].z * vv[j].z,
                                                    bv[j].z + kv[j].z + 1e-20f);
                    float p3 = rv[j].w * __fdividef(av[j].w + kv[j].w * vv[j].w,
                                                    bv[j].w + kv[j].w + 1e-20f);
                    prod_store_row(Phi, Plo, row, lane, p0, p1, p2, p3);
                }
                if (ib < 3) {
#pragma unroll
                    for (int j = 0; j < 4; ++j) {
                        int i = (ib + 1) * 4 + j;
                        int e = base + r0w + i;
                        int ec = (e < E) ? e : (E - 1);
                        int si = __shfl_sync(0xffffffffu, idxv, i);
                        int vi = __shfl_sync(0xffffffffu, idxv, 16 + i);
                        av[j] = __ldcs((const float4*)(ah) + (size_t)ec * 32 + lane);
                        bv[j] = __ldcs((const float4*)(bh) + (size_t)ec * 32 + lane);
                        kv[j] = *((const float4*)(g_K) + (size_t)si * 32 + lane);
                        vv[j] = *((const float4*)(g_V) + (size_t)vi * 32 + lane);
                        rv[j] = *((const float4*)(g_R) + (size_t)si * 32 + lane);
                    }
                }
            }
            __syncwarp();
            if (lane == 0) mbar_arrive(ctrl + (b * 2 + h) * 8);   // full[b][h]
        }
    } else {
        // ================= consumer: wm group handles half wm =================
        int wm = wid >> 2, wn = wid & 3;
        int col0 = wn * 32 + (lane & 3) * 8;   // 8 consecutive output cols
        uint32_t pf[2] = {0, 0};
        int it = 0;
        for (int tile = blockIdx.x; tile < nTiles; tile += gridDim.x, ++it) {
            int b = it & 1;
            mbar_wait(ctrl + (b * 2 + wm) * 8, pf[b]); pf[b] ^= 1;
            uint32_t sPhi = sP + b * 65536;
            uint32_t sPlo = sPhi + 32768;

            float acc[4][4][4];
            consumer_gemm(sPhi, sPlo, sWhi, sWlo, wm, wn, lane, acc);

            __syncwarp();
            if (lane == 0) mbar_arrive(ctrl + 32 + (b * 2 + wm) * 8);  // empty[b][wm]

            int base = tile * TILE;
#pragma unroll
            for (int mb = 0; mb < 4; ++mb) {
                int rA = base + wm * 64 + mb * 16 + (lane >> 2);
                int rB = rA + 8;
                if (rA < E) {
                    float4 fa = make_float4(acc[mb][0][0], acc[mb][0][1],
                                            acc[mb][1][0], acc[mb][1][1]);
                    float4 fb = make_float4(acc[mb][2][0], acc[mb][2][1],
                                            acc[mb][3][0], acc[mb][3][1]);
                    __stcs((float4*)(out + (size_t)rA * CDIM + col0), fa);
                    __stcs((float4*)(out + (size_t)rA * CDIM + col0 + 4), fb);
                }
                if (rB < E) {
                    float4 fc = make_float4(acc[mb][0][2], acc[mb][0][3],
                                            acc[mb][1][2], acc[mb][1][3]);
                    float4 fd = make_float4(acc[mb][2][2], acc[mb][2][3],
                                            acc[mb][3][2], acc[mb][3][3]);
                    __stcs((float4*)(out + (size_t)rB * CDIM + col0), fc);
                    __stcs((float4*)(out + (size_t)rB * CDIM + col0 + 4), fd);
                }
            }
        }
    }
}

// ================= node kernel: per-warp arrives (count-8 mbarriers) =================
// ctrl: full[b] = ctrl + b*8 (count 8) ; empty[b] = ctrl + 16 + b*8 (count 8)
__global__ __launch_bounds__(WSTHREADS, 1)
void node_ws_kernel(const float* __restrict__ x, const float* __restrict__ prevx,
                    const float* __restrict__ Wk, const float* __restrict__ Wv,
                    const float* __restrict__ Wr,
                    const float* __restrict__ tmk, const float* __restrict__ tmv,
                    const float* __restrict__ tmr, const float* __restrict__ tw,
                    const void* ip, const void* Tp,
                    int N, int nTiles) {
    extern __shared__ __align__(128) char sm[];
    char* Whi = sm;
    char* Wlo = sm + 32768;
    char* Pb  = sm + 65536;
    uint32_t ctrl = smem_u32(sm + 196608);
    uint32_t sWhi = smem_u32(Whi), sWlo = smem_u32(Wlo);
    uint32_t sP = smem_u32(Pb);

    int tid = threadIdx.x;
    int wid = tid >> 5, lane = tid & 31;
    int mat = blockIdx.y;
    const float* W  = (mat == 0) ? Wk  : (mat == 1) ? Wv  : Wr;
    const float* tm = (mat == 0) ? tmk : (mat == 1) ? tmv : tmr;
    float* dstG = (mat == 0) ? g_K : (mat == 1) ? g_V : g_R;

    if (tid == 0) {
        mbar_init(ctrl + 0, 8);   // full0
        mbar_init(ctrl + 8, 8);   // full1
        mbar_init(ctrl + 16, 8);  // empty0
        mbar_init(ctrl + 24, 8);  // empty1
    }
    fill_W_split(Whi, Wlo, W, tid, WSTHREADS);
    __syncthreads();

    if (wid >= 8) {
        int pw = wid - 8;
        float4 tv = *((const float4*)tm + lane);
        uint32_t pe[2] = {0, 0};
        int it = 0;
        for (int tile = blockIdx.x; tile < nTiles; tile += gridDim.x, ++it) {
            int b = it & 1;
            char* Phi = Pb + b * 65536;
            char* Plo = Phi + 32768;
            int base = tile * TILE;

            float4 xv[4], pv[4];
#pragma unroll
            for (int j = 0; j < 4; ++j) {
                int node = base + pw + 8 * j;
                int nc = (node < N) ? node : (N - 1);
                xv[j] = *((const float4*)(x)     + (size_t)nc * 32 + lane);
                pv[j] = *((const float4*)(prevx) + (size_t)nc * 32 + lane);
            }

            if (it >= 2) { mbar_wait(ctrl + 16 + b * 8, pe[b]); pe[b] ^= 1; }
#pragma unroll
            for (int ib = 0; ib < 4; ++ib) {
#pragma unroll
                for (int j = 0; j < 4; ++j) {
                    int i = ib * 4 + j;
                    int row = pw + 8 * i;
                    float p0 = pv[j].x + tv.x * (xv[j].x - pv[j].x);
                    float p1 = pv[j].y + tv.y * (xv[j].y - pv[j].y);
                    float p2 = pv[j].z + tv.z * (xv[j].z - pv[j].z);
                    float p3 = pv[j].w + tv.w * (xv[j].w - pv[j].w);
                    prod_store_row(Phi, Plo, row, lane, p0, p1, p2, p3);
                }
                if (ib < 3) {
#pragma unroll
                    for (int j = 0; j < 4; ++j) {
                        int i = (ib + 1) * 4 + j;
                        int node = base + pw + 8 * i;
                        int nc = (node < N) ? node : (N - 1);
                        xv[j] = *((const float4*)(x)     + (size_t)nc * 32 + lane);
                        pv[j] = *((const float4*)(prevx) + (size_t)nc * 32 + lane);
                    }
                }
            }
            __syncwarp();
            if (lane == 0) mbar_arrive(ctrl + b * 8);   // full[b], count 8
        }
    } else {
        int wm = wid >> 2, wn = wid & 3;
        int col0 = wn * 32 + (lane & 3) * 8;
        float wreg[8];
        if (mat == 1) {
            int iv = *(const int*)ip;
            int Tv = *(const int*)Tp;
            float f = -(float)(Tv - iv - 1);
#pragma unroll
            for (int i = 0; i < 8; ++i) wreg[i] = __expf(f * tw[col0 + i]);
        }
        uint32_t pf[2] = {0, 0};
        int it = 0;
        for (int tile = blockIdx.x; tile < nTiles; tile += gridDim.x, ++it) {
            int b = it & 1;
            mbar_wait(ctrl + b * 8, pf[b]); pf[b] ^= 1;
            uint32_t sPhi = sP + b * 65536;
            uint32_t sPlo = sPhi + 32768;

            float acc[4][4][4];
            consumer_gemm(sPhi, sPlo, sWhi, sWlo, wm, wn, lane, acc);

            __syncwarp();
            if (lane == 0) mbar_arrive(ctrl + 16 + b * 8);  // empty[b], count 8

            int base = tile * TILE;
#pragma unroll
            for (int mb = 0; mb < 4; ++mb) {
#pragma unroll
                for (int hh = 0; hh < 2; ++hh) {
                    int row = base + wm * 64 + mb * 16 + (lane >> 2) + hh * 8;
                    if (row >= N) continue;
                    float v8[8];
                    v8[0] = acc[mb][0][hh * 2];  v8[1] = acc[mb][0][hh * 2 + 1];
                    v8[2] = acc[mb][1][hh * 2];  v8[3] = acc[mb][1][hh * 2 + 1];
                    v8[4] = acc[mb][2][hh * 2];  v8[5] = acc[mb][2][hh * 2 + 1];
                    v8[6] = acc[mb][3][hh * 2];  v8[7] = acc[mb][3][hh * 2 + 1];
                    float o8[8];
                    if (mat == 0) {
#pragma unroll
                        for (int i = 0; i < 8; ++i) o8[i] = __expf(fminf(v8[i], 60.0f));
                    } else if (mat == 1) {
#pragma unroll
                        for (int i = 0; i < 8; ++i) o8[i] = v8[i] * wreg[i];
                    } else {
#pragma unroll
                        for (int i = 0; i < 8; ++i)
                            o8[i] = __fdividef(1.0f, 1.0f + __expf(-v8[i]));
                    }
                    float4 fa = make_float4(o8[0], o8[1], o8[2], o8[3]);
                    float4 fb = make_float4(o8[4], o8[5], o8[6], o8[7]);
                    *(float4*)(dstG + (size_t)row * CDIM + col0)     = fa;
                    *(float4*)(dstG + (size_t)row * CDIM + col0 + 4) = fb;
                }
            }
        }
    }
}

// ---------------- launch ----------------
extern "C" void kernel_launch(void* const* d_in, const int* in_sizes, int n_in,
                              void* d_out, int out_size) {
    const float* x      = (const float*)d_in[0];
    const float* prev_x = (const float*)d_in[1];
    const float* ah     = (const float*)d_in[2];
    const float* bh     = (const float*)d_in[3];
    const float* Wk     = (const float*)d_in[4];
    const float* Wv     = (const float*)d_in[5];
    const float* Wr     = (const float*)d_in[6];
    const float* Wo     = (const float*)d_in[7];
    const float* tmk    = (const float*)d_in[8];
    const float* tmv    = (const float*)d_in[9];
    const float* tmr    = (const float*)d_in[10];
    const float* tw     = (const float*)d_in[11];
    const void*  s      = d_in[12];
    const void*  t      = d_in[13];
    const void*  ip     = d_in[14];
    const void*  Tp     = d_in[15];

    int N = in_sizes[0] / CDIM;
    int E = in_sizes[2] / CDIM;

    cudaFuncSetAttribute(edge_ws_kernel, cudaFuncAttributeMaxDynamicSharedMemorySize, WS_SMEM);
    cudaFuncSetAttribute(node_ws_kernel, cudaFuncAttributeMaxDynamicSharedMemorySize, WS_SMEM);

    int nTilesN = (N + TILE - 1) / TILE;
    dim3 ngrid(49, 3);
    node_ws_kernel<<<ngrid, WSTHREADS, WS_SMEM>>>(x, prev_x, Wk, Wv, Wr,
                                                  tmk, tmv, tmr, tw, ip, Tp,
                                                  N, nTilesN);

    int nTiles = (E + TILE - 1) / TILE;
    edge_ws_kernel<<<GRIDX, WSTHREADS, WS_SMEM>>>(ah, bh, Wo, (float*)d_out,
                                                  s, t, E, nTiles);
}